// round 1
// baseline (speedup 1.0000x reference)
#include <cuda_runtime.h>
#include <math.h>

#define BDIM 8
#define HW 64
#define CMID 576
#define CCAT 1632
#define EPSV 1e-5f

// Scratch (device globals: allocation-free per harness rules)
__device__ float g_cat1[BDIM * CMID * HW * HW];   //  75.5 MB
__device__ float g_cat2[BDIM * CCAT * HW * HW];   // 213.9 MB
__device__ float g_mid [BDIM * CMID * HW * HW];   //  75.5 MB
__device__ float g_mid2[BDIM * CMID * HW * HW];   //  75.5 MB
__device__ float g_small[BDIM * HW * HW];

// ---------------------------------------------------------------------------
// cat1 = [coarse_m (384ch) ; raw_x 8x8 patch grid, patch-major (192ch)]
// patches[b, (gy*8+gx)*3+cc, ph, pw] = raw_x[b, cc, gy*64+ph, gx*64+pw]
// ---------------------------------------------------------------------------
__global__ void pack_cat1(const float* __restrict__ coarse,
                          const float* __restrict__ raw) {
    int idx = blockIdx.x * blockDim.x + threadIdx.x;
    const int N = BDIM * CMID * HW * HW;
    if (idx >= N) return;
    int x = idx & 63;
    int y = (idx >> 6) & 63;
    int c = (idx >> 12) % CMID;
    int b = idx / (CMID * HW * HW);
    float v;
    if (c < 384) {
        v = coarse[((b * 384 + c) << 12) + (y << 6) + x];
    } else {
        int pc = c - 384;
        int gy = pc / 24;
        int r  = pc - gy * 24;
        int gx = r / 3;
        int cc = r - gx * 3;
        v = raw[((b * 3 + cc) * 512 + gy * 64 + y) * 512 + gx * 64 + x];
    }
    g_cat1[idx] = v;
}

// ---------------------------------------------------------------------------
// cat2 side slices: ch [0,768) <- x2_2 ; ch [1344,1632) <- x3_1
// (the dec conv writes ch [768,1344) directly)
// ---------------------------------------------------------------------------
__global__ void pack_sides(const float* __restrict__ x2,
                           const float* __restrict__ x3) {
    int idx = blockIdx.x * blockDim.x + threadIdx.x;
    const int N2 = BDIM * 768 * HW * HW;
    const int N3 = BDIM * 288 * HW * HW;
    if (idx < N2) {
        int b = idx / (768 * 4096);
        int r = idx - b * 768 * 4096;
        g_cat2[b * CCAT * 4096 + r] = x2[idx];
    } else if (idx < N2 + N3) {
        int j = idx - N2;
        int b = j / (288 * 4096);
        int r = j - b * 288 * 4096;
        g_cat2[b * CCAT * 4096 + 1344 * 4096 + r] = x3[j];
    }
}

// ---------------------------------------------------------------------------
// conv3x3 (pad 1) + folded BN. Implicit-GEMM style tiling:
//   block = 64 couts x one image row (64 px) for one (b, y)
//   128 threads: thread tile = 4 couts x 8 x-positions (32 accum regs)
//   K loop in chunks of 8 cin: warps 0-1 stage weights, warps 2-3 stage the
//   3 haloed input rows into smem.
// ---------------------------------------------------------------------------
__global__ void __launch_bounds__(128)
conv3x3_bn(const float* __restrict__ in, int Cin,
           const float* __restrict__ W,
           const float* __restrict__ gam, const float* __restrict__ bet,
           const float* __restrict__ mu,  const float* __restrict__ var,
           float* __restrict__ out, int Ctot, int Coff) {
    __shared__ float s_in[8][3][72];   // [cin][ky][x=-1..64], padded
    __shared__ float s_w[8][9][64];    // [cin][ky*3+kx][cout]

    int tid = threadIdx.x;
    int cb  = blockIdx.x * 64;         // cout base
    int by  = blockIdx.y;
    int b   = by >> 6;
    int y   = by & 63;

    int tx = tid & 7;                  // x-group
    int ty = tid >> 3;                 // cout-group
    int x0 = tx << 3;

    float acc[4][8];
#pragma unroll
    for (int q = 0; q < 4; q++)
#pragma unroll
        for (int j = 0; j < 8; j++) acc[q][j] = 0.f;

    const float* wbase = W + (size_t)(cb + (tid & 63)) * Cin * 9;
    const float* ibb   = in + (size_t)b * Cin * 4096;

    int nchunks = Cin >> 3;
    for (int ch = 0; ch < nchunks; ch++) {
        int cin0 = ch << 3;
        __syncthreads();
        if (tid < 64) {
            // 72 contiguous floats: w[cout][cin0..cin0+7][0..8]
            const float4* wp = (const float4*)(wbase + cin0 * 9);
#pragma unroll
            for (int i = 0; i < 18; i++) {
                float4 f = wp[i];
                int e = i * 4;
                s_w[(e + 0) / 9][(e + 0) % 9][tid] = f.x;
                s_w[(e + 1) / 9][(e + 1) % 9][tid] = f.y;
                s_w[(e + 2) / 9][(e + 2) % 9][tid] = f.z;
                s_w[(e + 3) / 9][(e + 3) % 9][tid] = f.w;
            }
        } else {
            int t2 = tid - 64;
            const float* ibase = ibb + (size_t)cin0 * 4096;
#pragma unroll
            for (int i = 0; i < 25; i++) {
                int e = t2 + (i << 6);
                if (e < 8 * 3 * 66) {
                    int c  = e / 198;
                    int r  = e - c * 198;
                    int ky = r / 66;
                    int xx = r - ky * 66;
                    int xg = xx - 1;
                    int yg = y + ky - 1;
                    float v = 0.f;
                    if ((unsigned)xg < 64u && (unsigned)yg < 64u)
                        v = ibase[c * 4096 + yg * 64 + xg];
                    s_in[c][ky][xx] = v;
                }
            }
        }
        __syncthreads();

#pragma unroll
        for (int c = 0; c < 8; c++) {
#pragma unroll
            for (int ky = 0; ky < 3; ky++) {
                float a[10];
                const float4* ap = (const float4*)&s_in[c][ky][x0];
                float4 a0 = ap[0], a1 = ap[1];
                a[0] = a0.x; a[1] = a0.y; a[2] = a0.z; a[3] = a0.w;
                a[4] = a1.x; a[5] = a1.y; a[6] = a1.z; a[7] = a1.w;
                a[8] = s_in[c][ky][x0 + 8];
                a[9] = s_in[c][ky][x0 + 9];
#pragma unroll
                for (int kx = 0; kx < 3; kx++) {
                    float4 wv = *(const float4*)&s_w[c][ky * 3 + kx][ty * 4];
#pragma unroll
                    for (int j = 0; j < 8; j++) {
                        float av = a[j + kx];
                        acc[0][j] += wv.x * av;
                        acc[1][j] += wv.y * av;
                        acc[2][j] += wv.z * av;
                        acc[3][j] += wv.w * av;
                    }
                }
            }
        }
    }

    // Epilogue: fold BN, write
#pragma unroll
    for (int q = 0; q < 4; q++) {
        int co = cb + ty * 4 + q;
        float s  = gam[co] * rsqrtf(var[co] + EPSV);
        float bi = bet[co] - mu[co] * s;
        float* op = out + (((size_t)b * Ctot + Coff + co) * 64 + y) * 64 + x0;
#pragma unroll
        for (int j = 0; j < 8; j++) op[j] = acc[q][j] * s + bi;
    }
}

// ---------------------------------------------------------------------------
// conv1x1 576 -> 1 (+bias) into g_small
// ---------------------------------------------------------------------------
__global__ void conv1x1_out(const float* __restrict__ in,
                            const float* __restrict__ w,
                            const float* __restrict__ bias) {
    int x  = threadIdx.x;
    int by = blockIdx.x;
    int b  = by >> 6;
    int y  = by & 63;
    const float* p = in + (size_t)b * CMID * 4096 + y * 64 + x;
    float s0 = 0.f, s1 = 0.f, s2 = 0.f, s3 = 0.f;
#pragma unroll 4
    for (int c = 0; c < CMID; c += 4) {
        s0 += p[(c + 0) * 4096] * w[c + 0];
        s1 += p[(c + 1) * 4096] * w[c + 1];
        s2 += p[(c + 2) * 4096] * w[c + 2];
        s3 += p[(c + 3) * 4096] * w[c + 3];
    }
    g_small[(b << 12) + (y << 6) + x] = (s0 + s1) + (s2 + s3) + bias[0];
}

// ---------------------------------------------------------------------------
// bilinear x8 upsample, align_corners=True (matches reference f32 arithmetic)
// ---------------------------------------------------------------------------
__global__ void upsample8(float* __restrict__ out) {
    int idx = blockIdx.x * blockDim.x + threadIdx.x;
    if (idx >= BDIM * 512 * 512) return;
    int ox = idx & 511;
    int oy = (idx >> 9) & 511;
    int b  = idx >> 18;
    const float sc = 63.0f / 511.0f;
    float fy = (float)oy * sc;
    float fx = (float)ox * sc;
    int y0 = (int)floorf(fy); int y1 = min(y0 + 1, 63);
    int x0 = (int)floorf(fx); int x1 = min(x0 + 1, 63);
    float wy = fy - (float)y0;
    float wx = fx - (float)x0;
    const float* p = g_small + (b << 12);
    float r0 = p[y0 * 64 + x0] * (1.f - wy) + p[y1 * 64 + x0] * wy;
    float r1 = p[y0 * 64 + x1] * (1.f - wy) + p[y1 * 64 + x1] * wy;
    out[idx] = r0 * (1.f - wx) + r1 * wx;
}

// ---------------------------------------------------------------------------
extern "C" void kernel_launch(void* const* d_in, const int* in_sizes, int n_in,
                              void* d_out, int out_size) {
    const float* coarse = (const float*)d_in[0];
    const float* x2     = (const float*)d_in[1];
    const float* x3     = (const float*)d_in[2];
    const float* raw    = (const float*)d_in[3];
    // d_in[4], d_in[5]: w_pred/b_pred -> dead branch, skipped
    const float* dec_w = (const float*)d_in[6];
    const float* dec_g = (const float*)d_in[7];
    const float* dec_b = (const float*)d_in[8];
    const float* dec_m = (const float*)d_in[9];
    const float* dec_v = (const float*)d_in[10];
    const float* cc_w  = (const float*)d_in[11];
    const float* cc_g  = (const float*)d_in[12];
    const float* cc_b  = (const float*)d_in[13];
    const float* cc_m  = (const float*)d_in[14];
    const float* cc_v  = (const float*)d_in[15];
    const float* o1_w  = (const float*)d_in[16];
    const float* o1_g  = (const float*)d_in[17];
    const float* o1_b  = (const float*)d_in[18];
    const float* o1_m  = (const float*)d_in[19];
    const float* o1_v  = (const float*)d_in[20];
    const float* o2_w  = (const float*)d_in[21];
    const float* o2_b  = (const float*)d_in[22];

    float *cat1, *cat2, *mid, *mid2;
    cudaGetSymbolAddress((void**)&cat1, g_cat1);
    cudaGetSymbolAddress((void**)&cat2, g_cat2);
    cudaGetSymbolAddress((void**)&mid,  g_mid);
    cudaGetSymbolAddress((void**)&mid2, g_mid2);

    const int Npix = BDIM * 64;  // (b, y) rows

    pack_cat1<<<(BDIM * CMID * 4096 + 255) / 256, 256>>>(coarse, raw);
    pack_sides<<<((BDIM * 768 * 4096 + BDIM * 288 * 4096) + 255) / 256, 256>>>(x2, x3);

    dim3 cgrid(CMID / 64, Npix);
    // dec: cat1(576) -> cat2 channels [768,1344)
    conv3x3_bn<<<cgrid, 128>>>(cat1, CMID, dec_w, dec_g, dec_b, dec_m, dec_v,
                               cat2, CCAT, 768);
    // cc: cat2(1632) -> mid(576)
    conv3x3_bn<<<cgrid, 128>>>(cat2, CCAT, cc_w, cc_g, cc_b, cc_m, cc_v,
                               mid, CMID, 0);
    // o1: mid(576) -> mid2(576)
    conv3x3_bn<<<cgrid, 128>>>(mid, CMID, o1_w, o1_g, o1_b, o1_m, o1_v,
                               mid2, CMID, 0);

    conv1x1_out<<<Npix, 64>>>(mid2, o2_w, o2_b);
    upsample8<<<(BDIM * 512 * 512 + 255) / 256, 256>>>((float*)d_out);
}

// round 2
// speedup vs baseline: 1.0015x; 1.0015x over previous
#include <cuda_runtime.h>
#include <math.h>

#define BDIM 8
#define HW 64
#define CMID 576
#define CCAT 1632
#define EPSV 1e-5f

// Scratch (device globals: allocation-free per harness rules)
__device__ float g_cat1[BDIM * CMID * HW * HW];   //  75.5 MB
__device__ float g_cat2[BDIM * CCAT * HW * HW];   // 213.9 MB
__device__ float g_mid [BDIM * CMID * HW * HW];   //  75.5 MB
__device__ float g_mid2[BDIM * CMID * HW * HW];   //  75.5 MB
__device__ float g_small[BDIM * HW * HW];

// ---------------------------------------------------------------------------
// cat1 = [coarse_m (384ch) ; raw_x 8x8 patch grid, patch-major (192ch)]
// patches[b, (gy*8+gx)*3+cc, ph, pw] = raw_x[b, cc, gy*64+ph, gx*64+pw]
// ---------------------------------------------------------------------------
__global__ void pack_cat1(const float* __restrict__ coarse,
                          const float* __restrict__ raw) {
    int idx = blockIdx.x * blockDim.x + threadIdx.x;
    const int N = BDIM * CMID * HW * HW;
    if (idx >= N) return;
    int x = idx & 63;
    int y = (idx >> 6) & 63;
    int c = (idx >> 12) % CMID;
    int b = idx / (CMID * HW * HW);
    float v;
    if (c < 384) {
        v = coarse[((b * 384 + c) << 12) + (y << 6) + x];
    } else {
        int pc = c - 384;
        int gy = pc / 24;
        int r  = pc - gy * 24;
        int gx = r / 3;
        int cc = r - gx * 3;
        v = raw[((b * 3 + cc) * 512 + gy * 64 + y) * 512 + gx * 64 + x];
    }
    g_cat1[idx] = v;
}

// ---------------------------------------------------------------------------
// cat2 side slices: ch [0,768) <- x2_2 ; ch [1344,1632) <- x3_1
// (the dec conv writes ch [768,1344) directly)
// ---------------------------------------------------------------------------
__global__ void pack_sides(const float* __restrict__ x2,
                           const float* __restrict__ x3) {
    int idx = blockIdx.x * blockDim.x + threadIdx.x;
    const int N2 = BDIM * 768 * HW * HW;
    const int N3 = BDIM * 288 * HW * HW;
    if (idx < N2) {
        int b = idx / (768 * 4096);
        int r = idx - b * 768 * 4096;
        g_cat2[b * CCAT * 4096 + r] = x2[idx];
    } else if (idx < N2 + N3) {
        int j = idx - N2;
        int b = j / (288 * 4096);
        int r = j - b * 288 * 4096;
        g_cat2[b * CCAT * 4096 + 1344 * 4096 + r] = x3[j];
    }
}

// ---------------------------------------------------------------------------
// conv3x3 (pad 1) + folded BN. Implicit-GEMM style tiling:
//   block = 64 couts x one image row (64 px) for one (b, y)
//   128 threads: thread tile = 4 couts x 8 x-positions (32 accum regs)
//   K loop in chunks of 8 cin: warps 0-1 stage weights, warps 2-3 stage the
//   3 haloed input rows into smem.
// ---------------------------------------------------------------------------
__global__ void __launch_bounds__(128)
conv3x3_bn(const float* __restrict__ in, int Cin,
           const float* __restrict__ W,
           const float* __restrict__ gam, const float* __restrict__ bet,
           const float* __restrict__ mu,  const float* __restrict__ var,
           float* __restrict__ out, int Ctot, int Coff) {
    __shared__ float s_in[8][3][72];   // [cin][ky][x=-1..64], padded
    __shared__ float s_w[8][9][64];    // [cin][ky*3+kx][cout]

    int tid = threadIdx.x;
    int cb  = blockIdx.x * 64;         // cout base
    int by  = blockIdx.y;
    int b   = by >> 6;
    int y   = by & 63;

    int tx = tid & 7;                  // x-group
    int ty = tid >> 3;                 // cout-group
    int x0 = tx << 3;

    float acc[4][8];
#pragma unroll
    for (int q = 0; q < 4; q++)
#pragma unroll
        for (int j = 0; j < 8; j++) acc[q][j] = 0.f;

    const float* wbase = W + (size_t)(cb + (tid & 63)) * Cin * 9;
    const float* ibb   = in + (size_t)b * Cin * 4096;

    int nchunks = Cin >> 3;
    for (int ch = 0; ch < nchunks; ch++) {
        int cin0 = ch << 3;
        __syncthreads();
        if (tid < 64) {
            // 72 contiguous floats: w[cout][cin0..cin0+7][0..8]
            const float4* wp = (const float4*)(wbase + cin0 * 9);
#pragma unroll
            for (int i = 0; i < 18; i++) {
                float4 f = wp[i];
                int e = i * 4;
                s_w[(e + 0) / 9][(e + 0) % 9][tid] = f.x;
                s_w[(e + 1) / 9][(e + 1) % 9][tid] = f.y;
                s_w[(e + 2) / 9][(e + 2) % 9][tid] = f.z;
                s_w[(e + 3) / 9][(e + 3) % 9][tid] = f.w;
            }
        } else {
            int t2 = tid - 64;
            const float* ibase = ibb + (size_t)cin0 * 4096;
#pragma unroll
            for (int i = 0; i < 25; i++) {
                int e = t2 + (i << 6);
                if (e < 8 * 3 * 66) {
                    int c  = e / 198;
                    int r  = e - c * 198;
                    int ky = r / 66;
                    int xx = r - ky * 66;
                    int xg = xx - 1;
                    int yg = y + ky - 1;
                    float v = 0.f;
                    if ((unsigned)xg < 64u && (unsigned)yg < 64u)
                        v = ibase[c * 4096 + yg * 64 + xg];
                    s_in[c][ky][xx] = v;
                }
            }
        }
        __syncthreads();

#pragma unroll
        for (int c = 0; c < 8; c++) {
#pragma unroll
            for (int ky = 0; ky < 3; ky++) {
                float a[10];
                const float4* ap = (const float4*)&s_in[c][ky][x0];
                float4 a0 = ap[0], a1 = ap[1];
                a[0] = a0.x; a[1] = a0.y; a[2] = a0.z; a[3] = a0.w;
                a[4] = a1.x; a[5] = a1.y; a[6] = a1.z; a[7] = a1.w;
                a[8] = s_in[c][ky][x0 + 8];
                a[9] = s_in[c][ky][x0 + 9];
#pragma unroll
                for (int kx = 0; kx < 3; kx++) {
                    float4 wv = *(const float4*)&s_w[c][ky * 3 + kx][ty * 4];
#pragma unroll
                    for (int j = 0; j < 8; j++) {
                        float av = a[j + kx];
                        acc[0][j] += wv.x * av;
                        acc[1][j] += wv.y * av;
                        acc[2][j] += wv.z * av;
                        acc[3][j] += wv.w * av;
                    }
                }
            }
        }
    }

    // Epilogue: fold BN, write
#pragma unroll
    for (int q = 0; q < 4; q++) {
        int co = cb + ty * 4 + q;
        float s  = gam[co] * rsqrtf(var[co] + EPSV);
        float bi = bet[co] - mu[co] * s;
        float* op = out + (((size_t)b * Ctot + Coff + co) * 64 + y) * 64 + x0;
#pragma unroll
        for (int j = 0; j < 8; j++) op[j] = acc[q][j] * s + bi;
    }
}

// ---------------------------------------------------------------------------
// conv1x1 576 -> 1 (+bias) into g_small
// ---------------------------------------------------------------------------
__global__ void conv1x1_out(const float* __restrict__ in,
                            const float* __restrict__ w,
                            const float* __restrict__ bias) {
    int x  = threadIdx.x;
    int by = blockIdx.x;
    int b  = by >> 6;
    int y  = by & 63;
    const float* p = in + (size_t)b * CMID * 4096 + y * 64 + x;
    float s0 = 0.f, s1 = 0.f, s2 = 0.f, s3 = 0.f;
#pragma unroll 4
    for (int c = 0; c < CMID; c += 4) {
        s0 += p[(c + 0) * 4096] * w[c + 0];
        s1 += p[(c + 1) * 4096] * w[c + 1];
        s2 += p[(c + 2) * 4096] * w[c + 2];
        s3 += p[(c + 3) * 4096] * w[c + 3];
    }
    g_small[(b << 12) + (y << 6) + x] = (s0 + s1) + (s2 + s3) + bias[0];
}

// ---------------------------------------------------------------------------
// bilinear x8 upsample, align_corners=True (matches reference f32 arithmetic)
// ---------------------------------------------------------------------------
__global__ void upsample8(float* __restrict__ out) {
    int idx = blockIdx.x * blockDim.x + threadIdx.x;
    if (idx >= BDIM * 512 * 512) return;
    int ox = idx & 511;
    int oy = (idx >> 9) & 511;
    int b  = idx >> 18;
    const float sc = 63.0f / 511.0f;
    float fy = (float)oy * sc;
    float fx = (float)ox * sc;
    int y0 = (int)floorf(fy); int y1 = min(y0 + 1, 63);
    int x0 = (int)floorf(fx); int x1 = min(x0 + 1, 63);
    float wy = fy - (float)y0;
    float wx = fx - (float)x0;
    const float* p = g_small + (b << 12);
    float r0 = p[y0 * 64 + x0] * (1.f - wy) + p[y1 * 64 + x0] * wy;
    float r1 = p[y0 * 64 + x1] * (1.f - wy) + p[y1 * 64 + x1] * wy;
    out[idx] = r0 * (1.f - wx) + r1 * wx;
}

// ---------------------------------------------------------------------------
extern "C" void kernel_launch(void* const* d_in, const int* in_sizes, int n_in,
                              void* d_out, int out_size) {
    const float* coarse = (const float*)d_in[0];
    const float* x2     = (const float*)d_in[1];
    const float* x3     = (const float*)d_in[2];
    const float* raw    = (const float*)d_in[3];
    // d_in[4], d_in[5]: w_pred/b_pred -> dead branch, skipped
    const float* dec_w = (const float*)d_in[6];
    const float* dec_g = (const float*)d_in[7];
    const float* dec_b = (const float*)d_in[8];
    const float* dec_m = (const float*)d_in[9];
    const float* dec_v = (const float*)d_in[10];
    const float* cc_w  = (const float*)d_in[11];
    const float* cc_g  = (const float*)d_in[12];
    const float* cc_b  = (const float*)d_in[13];
    const float* cc_m  = (const float*)d_in[14];
    const float* cc_v  = (const float*)d_in[15];
    const float* o1_w  = (const float*)d_in[16];
    const float* o1_g  = (const float*)d_in[17];
    const float* o1_b  = (const float*)d_in[18];
    const float* o1_m  = (const float*)d_in[19];
    const float* o1_v  = (const float*)d_in[20];
    const float* o2_w  = (const float*)d_in[21];
    const float* o2_b  = (const float*)d_in[22];

    float *cat1, *cat2, *mid, *mid2;
    cudaGetSymbolAddress((void**)&cat1, g_cat1);
    cudaGetSymbolAddress((void**)&cat2, g_cat2);
    cudaGetSymbolAddress((void**)&mid,  g_mid);
    cudaGetSymbolAddress((void**)&mid2, g_mid2);

    const int Npix = BDIM * 64;  // (b, y) rows

    pack_cat1<<<(BDIM * CMID * 4096 + 255) / 256, 256>>>(coarse, raw);
    pack_sides<<<((BDIM * 768 * 4096 + BDIM * 288 * 4096) + 255) / 256, 256>>>(x2, x3);

    dim3 cgrid(CMID / 64, Npix);
    // dec: cat1(576) -> cat2 channels [768,1344)
    conv3x3_bn<<<cgrid, 128>>>(cat1, CMID, dec_w, dec_g, dec_b, dec_m, dec_v,
                               cat2, CCAT, 768);
    // cc: cat2(1632) -> mid(576)
    conv3x3_bn<<<cgrid, 128>>>(cat2, CCAT, cc_w, cc_g, cc_b, cc_m, cc_v,
                               mid, CMID, 0);
    // o1: mid(576) -> mid2(576)
    conv3x3_bn<<<cgrid, 128>>>(mid, CMID, o1_w, o1_g, o1_b, o1_m, o1_v,
                               mid2, CMID, 0);

    conv1x1_out<<<Npix, 64>>>(mid2, o2_w, o2_b);
    upsample8<<<(BDIM * 512 * 512 + 255) / 256, 256>>>((float*)d_out);
}

// round 5
// speedup vs baseline: 3.5842x; 3.5788x over previous
#include <cuda_runtime.h>
#include <math.h>
#include <stdint.h>

#define BDIM 8
#define HW 64
#define CMID 576
#define CCAT 1632
#define EPSV 1e-5f

// ---------------------------------------------------------------------------
// Scratch (device globals: allocation-free per harness rules)
// ---------------------------------------------------------------------------
__device__ float g_cat1[BDIM * CMID * HW * HW];
__device__ float g_cat2[BDIM * CCAT * HW * HW];
__device__ float g_mid [BDIM * CMID * HW * HW];
__device__ float g_mid2[BDIM * CMID * HW * HW];
__device__ float g_small[BDIM * HW * HW];
__device__ float g_wt_dec[9 * CMID * CMID];
__device__ float g_wt_cc [9 * CMID * CCAT];
__device__ float g_wt_o1 [9 * CMID * CMID];

// ---------------------------------------------------------------------------
// helpers
// ---------------------------------------------------------------------------
__device__ __forceinline__ uint32_t f2tf32(float f) {
    uint32_t o;
    asm("cvt.rna.tf32.f32 %0, %1;" : "=r"(o) : "f"(f));
    return o;
}
__device__ __forceinline__ void mma_tf32(float* d, const uint32_t* a, const uint32_t* b) {
    asm volatile(
        "mma.sync.aligned.m16n8k8.row.col.f32.tf32.tf32.f32 "
        "{%0,%1,%2,%3}, {%4,%5,%6,%7}, {%8,%9}, {%0,%1,%2,%3};"
        : "+f"(d[0]), "+f"(d[1]), "+f"(d[2]), "+f"(d[3])
        : "r"(a[0]), "r"(a[1]), "r"(a[2]), "r"(a[3]), "r"(b[0]), "r"(b[1]));
}

// ---------------------------------------------------------------------------
// Weight transpose + tf32 round: OIHW [co][ci][p] -> [p][co][ci]
// ---------------------------------------------------------------------------
__global__ void wtrans(const float* __restrict__ w, float* __restrict__ wt, int CoCi) {
    __shared__ float s[2304];
    int base = blockIdx.x * 256;
    int t = threadIdx.x;
    for (int i = t; i < 2304; i += 256) s[i] = w[(size_t)base * 9 + i];
    __syncthreads();
#pragma unroll
    for (int p = 0; p < 9; p++)
        wt[(size_t)p * CoCi + base + t] = __uint_as_float(f2tf32(s[t * 9 + p]));
}

// ---------------------------------------------------------------------------
// pack kernels
// ---------------------------------------------------------------------------
__global__ void pack_cat1(const float* __restrict__ coarse,
                          const float* __restrict__ raw) {
    int idx = blockIdx.x * blockDim.x + threadIdx.x;
    const int N = BDIM * CMID * HW * HW;
    if (idx >= N) return;
    int x = idx & 63;
    int y = (idx >> 6) & 63;
    int c = (idx >> 12) % CMID;
    int b = idx / (CMID * HW * HW);
    float v;
    if (c < 384) {
        v = coarse[((b * 384 + c) << 12) + (y << 6) + x];
    } else {
        int pc = c - 384;
        int gy = pc / 24;
        int r  = pc - gy * 24;
        int gx = r / 3;
        int cc = r - gx * 3;
        v = raw[((b * 3 + cc) * 512 + gy * 64 + y) * 512 + gx * 64 + x];
    }
    g_cat1[idx] = v;
}

__global__ void pack_sides(const float* __restrict__ x2,
                           const float* __restrict__ x3) {
    int idx = blockIdx.x * blockDim.x + threadIdx.x;
    const int N2 = BDIM * 768 * HW * HW;
    const int N3 = BDIM * 288 * HW * HW;
    if (idx < N2) {
        int b = idx / (768 * 4096);
        int r = idx - b * 768 * 4096;
        g_cat2[b * CCAT * 4096 + r] = x2[idx];
    } else if (idx < N2 + N3) {
        int j = idx - N2;
        int b = j / (288 * 4096);
        int r = j - b * 288 * 4096;
        g_cat2[b * CCAT * 4096 + 1344 * 4096 + r] = x3[j];
    }
}

// ---------------------------------------------------------------------------
// conv3x3 + folded BN via mma.sync tf32 implicit GEMM.
//   CTA: M=256 pixels (4 rows of one image) x N=64 couts; 512 thr, 16 warps.
//   Warp grid 8(M) x 2(N): warp tile 32x32 -> 2 m-frags x 4 n-frags m16n8k8.
//   K loop: cin chunks of 16. Per chunk: stage halo (16c x 6r x 66x, tf32)
//   + all-9-position B tiles; A fragments read straight from halo with
//   (ky,kx) shifts. Next chunk's globals prefetched into regs during mma.
// ---------------------------------------------------------------------------
#define HALO_ROWP 68
#define HALO_CSTR (6 * HALO_ROWP)         // 408
#define HALO_F    (16 * HALO_CSTR)        // 6528 floats
#define B_NSTR    72
#define B_POSSTR  (16 * B_NSTR)           // 1152
#define B_F       (9 * B_POSSTR)          // 10368 floats
#define SMEM_BYTES ((HALO_F + B_F) * 4)   // 67584
#define HITER 13                          // ceil(6336/512)
#define BITER 18                          // 9216/512

__global__ void __launch_bounds__(512, 1)
conv3x3_tc(const float* __restrict__ in, int Cin,
           const float* __restrict__ wt,
           const float* __restrict__ gam, const float* __restrict__ bet,
           const float* __restrict__ mu,  const float* __restrict__ var,
           float* __restrict__ out, int Ctot, int Coff) {
    extern __shared__ float sm[];
    float* sh = sm;            // halo
    float* sB = sm + HALO_F;   // B tiles

    int tid = threadIdx.x;
    int wid = tid >> 5;
    int lid = tid & 31;
    int l4  = lid >> 2;
    int kc  = lid & 3;
    int mw  = wid & 7;          // 8 m-warps
    int nw  = wid >> 3;         // 2 n-warps

    int tile = blockIdx.x;      // 128 tiles: b = t>>4, 4 rows each
    int b  = tile >> 4;
    int y0 = (tile & 15) << 2;
    int cbase = blockIdx.y * 64;

    const float* ib = in + (size_t)b * Cin * 4096;

    float d[2][4][4];
#pragma unroll
    for (int mi = 0; mi < 2; mi++)
#pragma unroll
        for (int ni = 0; ni < 4; ni++)
#pragma unroll
            for (int j = 0; j < 4; j++) d[mi][ni][j] = 0.f;

    // per-thread A-fragment geometry (same for every chunk)
    int mm0 = mw * 32 + l4;         // mi=0
    int mm1 = mw * 32 + 16 + l4;    // mi=1
    int ya0 = mm0 >> 6, xa0 = mm0 & 63;
    int ya1 = mm1 >> 6, xa1 = mm1 & 63;

    float hreg[HITER];
    float breg[BITER];

    // prefetch chunk 0
    {
#pragma unroll
        for (int i = 0; i < HITER; i++) {
            int e = tid + i * 512;
            float v = 0.f;
            if (e < 6336) {
                int c   = e / 396;
                int rem = e - c * 396;
                int r   = rem / 66;
                int xx  = rem - r * 66;
                int yg = y0 - 1 + r;
                int xg = xx - 1;
                if ((unsigned)yg < 64u && (unsigned)xg < 64u)
                    v = ib[(size_t)c * 4096 + yg * 64 + xg];
            }
            hreg[i] = v;
        }
#pragma unroll
        for (int i = 0; i < BITER; i++) {
            int idx = tid + i * 512;
            int k = idx & 15;
            int n = (idx >> 4) & 63;
            int pos = idx >> 10;
            breg[i] = wt[((size_t)pos * CMID + cbase + n) * Cin + k];
        }
    }

    int nchunks = Cin >> 4;
    for (int ch = 0; ch < nchunks; ch++) {
        __syncthreads();      // previous chunk's smem readers done
        // ---- store staged regs to smem
#pragma unroll
        for (int i = 0; i < HITER; i++) {
            int e = tid + i * 512;
            if (e < 6336) {
                int c   = e / 396;
                int rem = e - c * 396;
                int r   = rem / 66;
                int xx  = rem - r * 66;
                sh[c * HALO_CSTR + r * HALO_ROWP + xx] =
                    __uint_as_float(f2tf32(hreg[i]));
            }
        }
#pragma unroll
        for (int i = 0; i < BITER; i++) {
            int idx = tid + i * 512;
            int k = idx & 15;
            int n = (idx >> 4) & 63;
            int pos = idx >> 10;
            sB[pos * B_POSSTR + k * B_NSTR + n] = breg[i];
        }
        __syncthreads();

        // ---- prefetch next chunk while mma runs
        if (ch + 1 < nchunks) {
            int ci0 = (ch + 1) << 4;
#pragma unroll
            for (int i = 0; i < HITER; i++) {
                int e = tid + i * 512;
                float v = 0.f;
                if (e < 6336) {
                    int c   = e / 396;
                    int rem = e - c * 396;
                    int r   = rem / 66;
                    int xx  = rem - r * 66;
                    int yg = y0 - 1 + r;
                    int xg = xx - 1;
                    if ((unsigned)yg < 64u && (unsigned)xg < 64u)
                        v = ib[(size_t)(ci0 + c) * 4096 + yg * 64 + xg];
                }
                hreg[i] = v;
            }
#pragma unroll
            for (int i = 0; i < BITER; i++) {
                int idx = tid + i * 512;
                int k = idx & 15;
                int n = (idx >> 4) & 63;
                int pos = idx >> 10;
                breg[i] = wt[((size_t)pos * CMID + cbase + n) * Cin + ci0 + k];
            }
        }

        // ---- compute: 9 positions x 2 k-steps x (2 m-frags x 4 n-frags)
#pragma unroll
        for (int pos = 0; pos < 9; pos++) {
            int ky = pos / 3;
            int kx = pos - ky * 3;
            const float* hb = sh + ky * HALO_ROWP + kx;
            const float* bb = sB + pos * B_POSSTR;
#pragma unroll
            for (int ks = 0; ks < 2; ks++) {
                int k0 = ks << 3;
                uint32_t A[2][4], B[4][2];
                {
                    const float* p0 = hb + (k0 + kc) * HALO_CSTR + ya0 * HALO_ROWP + xa0;
                    A[0][0] = __float_as_uint(p0[0]);
                    A[0][1] = __float_as_uint(p0[8]);
                    A[0][2] = __float_as_uint(p0[4 * HALO_CSTR]);
                    A[0][3] = __float_as_uint(p0[4 * HALO_CSTR + 8]);
                    const float* p1 = hb + (k0 + kc) * HALO_CSTR + ya1 * HALO_ROWP + xa1;
                    A[1][0] = __float_as_uint(p1[0]);
                    A[1][1] = __float_as_uint(p1[8]);
                    A[1][2] = __float_as_uint(p1[4 * HALO_CSTR]);
                    A[1][3] = __float_as_uint(p1[4 * HALO_CSTR + 8]);
                }
#pragma unroll
                for (int ni = 0; ni < 4; ni++) {
                    const float* pb = bb + (k0 + kc) * B_NSTR + nw * 32 + ni * 8 + l4;
                    B[ni][0] = __float_as_uint(pb[0]);
                    B[ni][1] = __float_as_uint(pb[4 * B_NSTR]);
                }
#pragma unroll
                for (int mi = 0; mi < 2; mi++)
#pragma unroll
                    for (int ni = 0; ni < 4; ni++)
                        mma_tf32(d[mi][ni], A[mi], B[ni]);
            }
        }
    }

    // ---- epilogue: fold BN, write. d[mi][ni]: rows (m, m+8), cols (c0, c0+1)
#pragma unroll
    for (int ni = 0; ni < 4; ni++) {
        int co0 = cbase + nw * 32 + ni * 8 + kc * 2;
        int co1 = co0 + 1;
        float s0 = gam[co0] * rsqrtf(var[co0] + EPSV);
        float bi0 = bet[co0] - mu[co0] * s0;
        float s1 = gam[co1] * rsqrtf(var[co1] + EPSV);
        float bi1 = bet[co1] - mu[co1] * s1;
        size_t p0 = ((size_t)b * Ctot + Coff + co0) << 12;
        size_t p1 = ((size_t)b * Ctot + Coff + co1) << 12;
#pragma unroll
        for (int mi = 0; mi < 2; mi++) {
            int m = mw * 32 + mi * 16 + l4;
            int row = y0 + (m >> 6);
            int x = m & 63;
            size_t o = (size_t)row * 64 + x;
            out[p0 + o]     = d[mi][ni][0] * s0 + bi0;
            out[p1 + o]     = d[mi][ni][1] * s1 + bi1;
            out[p0 + o + 8] = d[mi][ni][2] * s0 + bi0;
            out[p1 + o + 8] = d[mi][ni][3] * s1 + bi1;
        }
    }
}

// ---------------------------------------------------------------------------
// conv1x1 576 -> 1 (+bias)
// ---------------------------------------------------------------------------
__global__ void conv1x1_out(const float* __restrict__ in,
                            const float* __restrict__ w,
                            const float* __restrict__ bias) {
    int x  = threadIdx.x;
    int by = blockIdx.x;
    int b  = by >> 6;
    int y  = by & 63;
    const float* p = in + (size_t)b * CMID * 4096 + y * 64 + x;
    float s0 = 0.f, s1 = 0.f, s2 = 0.f, s3 = 0.f;
#pragma unroll 4
    for (int c = 0; c < CMID; c += 4) {
        s0 += p[(c + 0) * 4096] * w[c + 0];
        s1 += p[(c + 1) * 4096] * w[c + 1];
        s2 += p[(c + 2) * 4096] * w[c + 2];
        s3 += p[(c + 3) * 4096] * w[c + 3];
    }
    g_small[(b << 12) + (y << 6) + x] = (s0 + s1) + (s2 + s3) + bias[0];
}

// ---------------------------------------------------------------------------
// bilinear x8 upsample (align_corners=True)
// ---------------------------------------------------------------------------
__global__ void upsample8(float* __restrict__ out) {
    int idx = blockIdx.x * blockDim.x + threadIdx.x;
    if (idx >= BDIM * 512 * 512) return;
    int ox = idx & 511;
    int oy = (idx >> 9) & 511;
    int b  = idx >> 18;
    const float sc = 63.0f / 511.0f;
    float fy = (float)oy * sc;
    float fx = (float)ox * sc;
    int y0 = (int)floorf(fy); int y1 = min(y0 + 1, 63);
    int x0 = (int)floorf(fx); int x1 = min(x0 + 1, 63);
    float wy = fy - (float)y0;
    float wx = fx - (float)x0;
    const float* p = g_small + (b << 12);
    float r0 = p[y0 * 64 + x0] * (1.f - wy) + p[y1 * 64 + x0] * wy;
    float r1 = p[y0 * 64 + x1] * (1.f - wy) + p[y1 * 64 + x1] * wy;
    out[idx] = r0 * (1.f - wx) + r1 * wx;
}

// ---------------------------------------------------------------------------
extern "C" void kernel_launch(void* const* d_in, const int* in_sizes, int n_in,
                              void* d_out, int out_size) {
    const float* coarse = (const float*)d_in[0];
    const float* x2     = (const float*)d_in[1];
    const float* x3     = (const float*)d_in[2];
    const float* raw    = (const float*)d_in[3];
    const float* dec_w = (const float*)d_in[6];
    const float* dec_g = (const float*)d_in[7];
    const float* dec_b = (const float*)d_in[8];
    const float* dec_m = (const float*)d_in[9];
    const float* dec_v = (const float*)d_in[10];
    const float* cc_w  = (const float*)d_in[11];
    const float* cc_g  = (const float*)d_in[12];
    const float* cc_b  = (const float*)d_in[13];
    const float* cc_m  = (const float*)d_in[14];
    const float* cc_v  = (const float*)d_in[15];
    const float* o1_w  = (const float*)d_in[16];
    const float* o1_g  = (const float*)d_in[17];
    const float* o1_b  = (const float*)d_in[18];
    const float* o1_m  = (const float*)d_in[19];
    const float* o1_v  = (const float*)d_in[20];
    const float* o2_w  = (const float*)d_in[21];
    const float* o2_b  = (const float*)d_in[22];

    float *cat1, *cat2, *mid, *mid2, *wt_dec, *wt_cc, *wt_o1;
    cudaGetSymbolAddress((void**)&cat1, g_cat1);
    cudaGetSymbolAddress((void**)&cat2, g_cat2);
    cudaGetSymbolAddress((void**)&mid,  g_mid);
    cudaGetSymbolAddress((void**)&mid2, g_mid2);
    cudaGetSymbolAddress((void**)&wt_dec, g_wt_dec);
    cudaGetSymbolAddress((void**)&wt_cc,  g_wt_cc);
    cudaGetSymbolAddress((void**)&wt_o1,  g_wt_o1);

    cudaFuncSetAttribute(conv3x3_tc,
                         cudaFuncAttributeMaxDynamicSharedMemorySize, SMEM_BYTES);

    wtrans<<<CMID * CMID / 256, 256>>>(dec_w, wt_dec, CMID * CMID);
    wtrans<<<CMID * CCAT / 256, 256>>>(cc_w,  wt_cc,  CMID * CCAT);
    wtrans<<<CMID * CMID / 256, 256>>>(o1_w,  wt_o1,  CMID * CMID);
    pack_cat1<<<(BDIM * CMID * 4096 + 255) / 256, 256>>>(coarse, raw);
    pack_sides<<<((BDIM * 768 * 4096 + BDIM * 288 * 4096) + 255) / 256, 256>>>(x2, x3);

    dim3 cgrid(128, 9);
    // dec: cat1(576) -> cat2 channels [768,1344)
    conv3x3_tc<<<cgrid, 512, SMEM_BYTES>>>(cat1, CMID, wt_dec,
        dec_g, dec_b, dec_m, dec_v, cat2, CCAT, 768);
    // cc: cat2(1632) -> mid(576)
    conv3x3_tc<<<cgrid, 512, SMEM_BYTES>>>(cat2, CCAT, wt_cc,
        cc_g, cc_b, cc_m, cc_v, mid, CMID, 0);
    // o1: mid(576) -> mid2(576)
    conv3x3_tc<<<cgrid, 512, SMEM_BYTES>>>(mid, CMID, wt_o1,
        o1_g, o1_b, o1_m, o1_v, mid2, CMID, 0);

    conv1x1_out<<<BDIM * 64, 64>>>(mid2, o2_w, o2_b);
    upsample8<<<(BDIM * 512 * 512 + 255) / 256, 256>>>((float*)d_out);
}